// round 14
// baseline (speedup 1.0000x reference)
#include <cuda_runtime.h>
#include <cuda_bf16.h>
#include <cstdint>

#define BBATCH 16
#define CCH 512
#define M_PIX (BBATCH*64*64)     // 65536
#define NPROJ 384
#define DK 64
#define DV 256
#define NKV 1024
#define NQ  4096
#define LOG2E 1.4426950408889634f

// ---------------- scratch (device globals) ----------------
__device__ __align__(256) __nv_bfloat16 g_xb   [M_PIX * CCH];       // x in bf16
__device__ __align__(256) __nv_bfloat16 g_theta[M_PIX * DK];        // theta*log2e [q][64]
__device__ __align__(256) __nv_bfloat16 g_phi  [BBATCH * NKV * DK]; // pooled phi [kv][d]
__device__ __align__(256) __nv_bfloat16 g_gT   [BBATCH * DV * NKV]; // pooled g^T [d][kv]
__device__ __align__(256) __nv_bfloat16 g_ag   [M_PIX * DV];        // attn out bf16
__device__ __align__(256) __nv_bfloat16 g_wcatT[NPROJ * CCH];       // proj weights^T
__device__ __align__(256) __nv_bfloat16 g_woT  [CCH * DV];          // w_o^T
__device__ float g_bcat[NPROJ];

// ---------------- helpers ----------------
__device__ __forceinline__ uint32_t smem_u32(const void* p) {
    uint32_t a;
    asm("{ .reg .u64 t; cvta.to.shared.u64 t, %1; cvt.u32.u64 %0, t; }" : "=r"(a) : "l"(p));
    return a;
}
#define SWZ(o) ((o) ^ (((o) >> 3) & 0x70))

__device__ __forceinline__ void ldsm_x4(uint32_t* r, uint32_t a) {
    asm volatile("ldmatrix.sync.aligned.m8n8.x4.shared.b16 {%0,%1,%2,%3}, [%4];"
        : "=r"(r[0]), "=r"(r[1]), "=r"(r[2]), "=r"(r[3]) : "r"(a));
}
__device__ __forceinline__ void mma16816(float* d, const uint32_t* a, uint32_t b0, uint32_t b1) {
    asm volatile("mma.sync.aligned.m16n8k16.row.col.f32.bf16.bf16.f32 "
        "{%0,%1,%2,%3}, {%4,%5,%6,%7}, {%8,%9}, {%0,%1,%2,%3};"
        : "+f"(d[0]), "+f"(d[1]), "+f"(d[2]), "+f"(d[3])
        : "r"(a[0]), "r"(a[1]), "r"(a[2]), "r"(a[3]), "r"(b0), "r"(b1));
}
__device__ __forceinline__ void cp16(uint32_t sa, const void* ga) {
    asm volatile("cp.async.cg.shared.global [%0], [%1], 16;" :: "r"(sa), "l"(ga));
}
#define CP_COMMIT() asm volatile("cp.async.commit_group;" ::: "memory")
#define CP_WAIT(n)  asm volatile("cp.async.wait_group %0;" :: "n"(n) : "memory")

__device__ __forceinline__ float ex2(float x) {
    float r;
    asm("ex2.approx.ftz.f32 %0, %1;" : "=f"(r) : "f"(x));
    return r;
}

// load [ROWS x 64] bf16 tile (row stride ld) into swizzled SMEM via cp.async
template <int ROWS>
__device__ __forceinline__ void load_tile_async(const __nv_bfloat16* __restrict__ src,
                                                size_t ld, uint32_t sbase, int tid) {
#pragma unroll
    for (int t = 0; t < ROWS / 32; t++) {
        int i = tid + t * 256;
        int row = i >> 3, c = i & 7;
        cp16(sbase + SWZ(row * 128 + c * 16), src + (size_t)row * ld + c * 8);
    }
}

// ------------- 128x128-tile bf16 HMMA GEMM, fp32 accum, 3-stage cp.async ----
// MODE 0: proj — theta(*log2e) direct + pooled phi + pooled/transposed gT (+bias)
// MODE 2: fp32 out = X + sig*(D+bias), x tile staged in last chunk
template <int MODE>
__global__ void __launch_bounds__(256, 2)
gemm128(const __nv_bfloat16* __restrict__ A, int lda,
        const __nv_bfloat16* __restrict__ B, int ldb,
        int K, int moff,
        const float* __restrict__ bias,
        const float* __restrict__ Xres, const float* __restrict__ sig,
        float* __restrict__ outf) {
    extern __shared__ char sm[];
    uint32_t base = smem_u32(sm);
    const uint32_t a_su[3] = {base, base + 16384, base + 32768};
    const uint32_t b_su[3] = {base + 49152, base + 65536, base + 81920};
    // x staging (MODE 2, last chunk): rows 0..63 from a_su[1], rows 64..127 from b_su[1]
    const uint32_t x_su[2] = {base + 16384, base + 65536};

    int tid = threadIdx.x, wid = tid >> 5, lane = tid & 31;
    int m0 = (blockIdx.y + moff) * 128, n0 = blockIdx.x * 128;
    int wm = wid & 3, wn = wid >> 2;
    int lr = lane & 15, lc = lane >> 4;

    const __nv_bfloat16* Ab = A + (size_t)m0 * lda;
    const __nv_bfloat16* Bb = B + (size_t)n0 * ldb;

    float acc[2][8][4];
#pragma unroll
    for (int i = 0; i < 2; i++)
#pragma unroll
        for (int j = 0; j < 8; j++)
#pragma unroll
            for (int e = 0; e < 4; e++) acc[i][j][e] = 0.f;

    const int nc = K >> 6;
    load_tile_async<128>(Ab, (size_t)lda, a_su[0], tid);
    load_tile_async<128>(Bb, (size_t)ldb, b_su[0], tid);
    CP_COMMIT();
    if (nc > 1) {
        load_tile_async<128>(Ab + 64, (size_t)lda, a_su[1], tid);
        load_tile_async<128>(Bb + 64, (size_t)ldb, b_su[1], tid);
        CP_COMMIT();
    }

#pragma unroll 3
    for (int c = 0; c < nc; c++) {
        if (c + 2 <= nc) { CP_WAIT(1); } else { CP_WAIT(0); }
        __syncthreads();

        if (MODE == 2 && c == nc - 1) {
            // stage fp32 x tile (128x128 = 64KB) into pipeline buffers 1+2
            // (all chunks except the current buf0 are consumed by now)
#pragma unroll
            for (int t = 0; t < 8; t++) {
                int i = tid + t * 256;
                int row = i >> 5, c4 = i & 31;
                cp16(x_su[0] + row * 512 + c4 * 16,
                     Xres + (size_t)(m0 + row) * CCH + n0 + c4 * 4);
                cp16(x_su[1] + row * 512 + c4 * 16,
                     Xres + (size_t)(m0 + 64 + row) * CCH + n0 + c4 * 4);
            }
            CP_COMMIT();
        }

        int buf = c % 3;
        uint32_t abase = a_su[buf], bbase = b_su[buf];
#pragma unroll
        for (int k16 = 0; k16 < 4; k16++) {
            uint32_t af[2][4];
#pragma unroll
            for (int mt = 0; mt < 2; mt++)
                ldsm_x4(af[mt], abase + SWZ((wm * 32 + mt * 16 + lr) * 128 + k16 * 32 + lc * 16));
            uint32_t bf4[4][4];
#pragma unroll
            for (int nt2 = 0; nt2 < 4; nt2++)
                ldsm_x4(bf4[nt2], bbase + SWZ((wn * 64 + nt2 * 16 + lr) * 128 + k16 * 32 + lc * 16));
#pragma unroll
            for (int mt = 0; mt < 2; mt++)
#pragma unroll
                for (int nt = 0; nt < 8; nt++)
                    mma16816(acc[mt][nt], af[mt], bf4[nt >> 1][nt & 1], bf4[nt >> 1][2 + (nt & 1)]);
        }

        if (c + 2 < nc) {
            int nb = (c + 2) % 3;
            load_tile_async<128>(Ab + (c + 2) * 64, (size_t)lda, a_su[nb], tid);
            load_tile_async<128>(Bb + (c + 2) * 64, (size_t)ldb, b_su[nb], tid);
            CP_COMMIT();
        }
    }

    if (MODE == 2) {
        CP_WAIT(0);        // x staging landed
        __syncthreads();
        float s = sig[0];
        int r0l = wm * 32 + (lane >> 2);
        int c0 = wn * 64 + (lane & 3) * 2;
#pragma unroll
        for (int mt = 0; mt < 2; mt++) {
#pragma unroll
            for (int half = 0; half < 2; half++) {
                int rowl = r0l + mt * 16 + half * 8;
                uint32_t xrow = x_su[rowl >> 6] + (rowl & 63) * 512;
                int grow = m0 + rowl;
#pragma unroll
                for (int nt = 0; nt < 8; nt++) {
                    int col = c0 + nt * 8;
                    float2 xv = *(const float2*)(sm + (xrow - base) + col * 4);
                    float2 o;
                    o.x = xv.x + s * (acc[mt][nt][half * 2 + 0] + bias[n0 + col]);
                    o.y = xv.y + s * (acc[mt][nt][half * 2 + 1] + bias[n0 + col + 1]);
                    *(float2*)(outf + (size_t)grow * CCH + n0 + col) = o;
                }
            }
        }
    }

    if (MODE == 0) {
        // proj epilogue with fused pooling
        int b = m0 >> 12;
        int kv0 = ((m0 >> 7) & 31) * 32;   // 32 pool windows per tile
        __nv_bfloat16* st = (__nv_bfloat16*)sm;
        __syncthreads();

        if (blockIdx.x == 0) {
            if (wn == 0) {
                // theta, pre-scaled by log2e for ex2-based softmax
#pragma unroll
                for (int mt = 0; mt < 2; mt++)
#pragma unroll
                    for (int half = 0; half < 2; half++) {
                        int row = m0 + wm * 32 + (lane >> 2) + mt * 16 + half * 8;
#pragma unroll
                        for (int nt = 0; nt < 8; nt++) {
                            int col = nt * 8 + (lane & 3) * 2;
                            *(__nv_bfloat162*)(g_theta + (size_t)row * DK + col) =
                                __floats2bfloat162_rn(
                                    (acc[mt][nt][half * 2] + bias[col]) * LOG2E,
                                    (acc[mt][nt][half * 2 + 1] + bias[col + 1]) * LOG2E);
                        }
                    }
            } else {
#pragma unroll
                for (int mt = 0; mt < 2; mt++)
#pragma unroll
                    for (int half = 0; half < 2; half++) {
                        int lrow = wm * 32 + (lane >> 2) + mt * 16 + half * 8;
#pragma unroll
                        for (int nt = 0; nt < 8; nt++) {
                            int lcol = nt * 8 + (lane & 3) * 2;   // 0..63
                            *(__nv_bfloat162*)(st + lrow * 72 + lcol) =
                                __floats2bfloat162_rn(acc[mt][nt][half * 2] + bias[64 + lcol],
                                                      acc[mt][nt][half * 2 + 1] + bias[65 + lcol]);
                        }
                    }
            }
            __syncthreads();
            int w = tid >> 3, d8 = (tid & 7) * 8;
            __align__(16) __nv_bfloat16 o[8];
#pragma unroll
            for (int j = 0; j < 8; j++) {
                int d = d8 + j;
                o[j] = __hmax(__hmax(st[(2 * w) * 72 + d], st[(2 * w + 1) * 72 + d]),
                              __hmax(st[(64 + 2 * w) * 72 + d], st[(65 + 2 * w) * 72 + d]));
            }
            *(uint4*)(g_phi + ((size_t)(b * NKV + kv0 + w)) * DK + d8) = *(uint4*)o;
        } else {
#pragma unroll
            for (int mt = 0; mt < 2; mt++)
#pragma unroll
                for (int half = 0; half < 2; half++) {
                    int lrow = wm * 32 + (lane >> 2) + mt * 16 + half * 8;
#pragma unroll
                    for (int nt = 0; nt < 8; nt++) {
                        int lcol = wn * 64 + nt * 8 + (lane & 3) * 2;   // 0..127
                        *(__nv_bfloat162*)(st + lrow * 130 + lcol) =
                            __floats2bfloat162_rn(acc[mt][nt][half * 2] + bias[n0 + lcol],
                                                  acc[mt][nt][half * 2 + 1] + bias[n0 + lcol + 1]);
                    }
                }
            __syncthreads();
            int dl = tid & 127, kvh = tid >> 7;
            int dg = (blockIdx.x - 1) * 128 + dl;
            __align__(16) __nv_bfloat16 o[16];
#pragma unroll
            for (int i = 0; i < 16; i++) {
                int w = kvh * 16 + i;
                o[i] = __hmax(__hmax(st[(2 * w) * 130 + dl], st[(2 * w + 1) * 130 + dl]),
                              __hmax(st[(64 + 2 * w) * 130 + dl], st[(65 + 2 * w) * 130 + dl]));
            }
            __nv_bfloat16* dst = g_gT + ((size_t)(b * DV + dg)) * NKV + kv0 + kvh * 16;
            *(uint4*)dst = ((uint4*)o)[0];
            *(uint4*)(dst + 8) = ((uint4*)o)[1];
        }
    }
}

// ------------- fused attention: ag = softmax(theta phi^T) g ----------------
#define ATTN_SMEM (99072)
__global__ void __launch_bounds__(256, 2) attn_fused(int toff) {
    extern __shared__ char sm[];
    uint32_t base = smem_u32(sm);
    const uint32_t th_s = base;
    const uint32_t ph_s[2] = {base + 8192, base + 16384};
    const uint32_t gt_s[2] = {base + 24576, base + 57344};
    const uint32_t p_s = base + 90112;
    float* wsum = (float*)(sm + 98304);   // [2][64]
    float* rinv = (float*)(sm + 98816);   // [64]

    int tid = threadIdx.x, wid = tid >> 5, lane = tid & 31;
    int lr = lane & 15, lc = lane >> 4;
    int tile = blockIdx.x + toff;
    int mbase = tile * 64;
    int b = tile >> 6;
    int wm = wid & 3, wn = wid >> 2;       // S phase
    int pm = wid & 1, pn = wid >> 1;       // PV phase

    const __nv_bfloat16* thp = g_theta + (size_t)mbase * DK;
    const __nv_bfloat16* php = g_phi + (size_t)b * NKV * DK;
    const __nv_bfloat16* gtp = g_gT + (size_t)b * DV * NKV;

    float O[2][8][4];
#pragma unroll
    for (int i = 0; i < 2; i++)
#pragma unroll
        for (int j = 0; j < 8; j++)
#pragma unroll
            for (int e = 0; e < 4; e++) O[i][j][e] = 0.f;
    float sum0 = 0.f, sum1 = 0.f;

    load_tile_async<64>(thp, DK, th_s, tid);
    load_tile_async<64>(php, DK, ph_s[0], tid);
    load_tile_async<256>(gtp, NKV, gt_s[0], tid);
    CP_COMMIT();

    for (int c = 0; c < 16; c++) {
        CP_WAIT(0);
        __syncthreads();   // chunk-c tiles visible; all warps done with c-1

        if (c + 1 < 16) {  // prefetch c+1 (overlaps S+PV of c)
            int nb = (c + 1) & 1;
            load_tile_async<64>(php + (size_t)(c + 1) * 64 * DK, DK, ph_s[nb], tid);
            load_tile_async<256>(gtp + (c + 1) * 64, NKV, gt_s[nb], tid);
            CP_COMMIT();
        }

        // ---- S phase ----
        float sacc[4][4];
#pragma unroll
        for (int j = 0; j < 4; j++)
#pragma unroll
            for (int e = 0; e < 4; e++) sacc[j][e] = 0.f;
        uint32_t pb = ph_s[c & 1];
#pragma unroll
        for (int k16 = 0; k16 < 4; k16++) {
            uint32_t af[4];
            ldsm_x4(af, th_s + SWZ((wm * 16 + lr) * 128 + k16 * 32 + lc * 16));
            uint32_t bf2[2][4];
#pragma unroll
            for (int nt2 = 0; nt2 < 2; nt2++)
                ldsm_x4(bf2[nt2], pb + SWZ((wn * 32 + nt2 * 16 + lr) * 128 + k16 * 32 + lc * 16));
#pragma unroll
            for (int nt = 0; nt < 4; nt++)
                mma16816(sacc[nt], af, bf2[nt >> 1][nt & 1], bf2[nt >> 1][2 + (nt & 1)]);
        }

        int srow = wm * 16 + (lane >> 2);
#pragma unroll
        for (int nt = 0; nt < 4; nt++) {
            int scol = wn * 32 + nt * 8 + (lane & 3) * 2;
            float e0 = ex2(sacc[nt][0]);
            float e1 = ex2(sacc[nt][1]);
            float e2 = ex2(sacc[nt][2]);
            float e3 = ex2(sacc[nt][3]);
            sum0 += e0 + e1;
            sum1 += e2 + e3;
            *(__nv_bfloat162*)(sm + (p_s - base) + SWZ(srow * 128 + scol * 2)) =
                __floats2bfloat162_rn(e0, e1);
            *(__nv_bfloat162*)(sm + (p_s - base) + SWZ((srow + 8) * 128 + scol * 2)) =
                __floats2bfloat162_rn(e2, e3);
        }
        __syncthreads();   // P(c) visible to all warps

        // ---- PV phase ----
        uint32_t gb = gt_s[c & 1];
#pragma unroll
        for (int k16 = 0; k16 < 4; k16++) {
            uint32_t paf[2][4];
#pragma unroll
            for (int mt = 0; mt < 2; mt++)
                ldsm_x4(paf[mt], p_s + SWZ((pm * 32 + mt * 16 + lr) * 128 + k16 * 32 + lc * 16));
            uint32_t gbf[4][4];
#pragma unroll
            for (int nt2 = 0; nt2 < 4; nt2++)
                ldsm_x4(gbf[nt2], gb + SWZ((pn * 64 + nt2 * 16 + lr) * 128 + k16 * 32 + lc * 16));
#pragma unroll
            for (int mt = 0; mt < 2; mt++)
#pragma unroll
                for (int nt = 0; nt < 8; nt++)
                    mma16816(O[mt][nt], paf[mt], gbf[nt >> 1][nt & 1], gbf[nt >> 1][2 + (nt & 1)]);
        }
    }

    // deterministic row-sum reduction
    sum0 += __shfl_xor_sync(0xffffffffu, sum0, 1);
    sum0 += __shfl_xor_sync(0xffffffffu, sum0, 2);
    sum1 += __shfl_xor_sync(0xffffffffu, sum1, 1);
    sum1 += __shfl_xor_sync(0xffffffffu, sum1, 2);
    if ((lane & 3) == 0) {
        wsum[wn * 64 + wm * 16 + (lane >> 2)] = sum0;
        wsum[wn * 64 + wm * 16 + 8 + (lane >> 2)] = sum1;
    }
    __syncthreads();
    if (tid < 64) rinv[tid] = 1.f / (wsum[tid] + wsum[64 + tid]);
    __syncthreads();

#pragma unroll
    for (int mt = 0; mt < 2; mt++) {
#pragma unroll
        for (int half = 0; half < 2; half++) {
            int row = pm * 32 + mt * 16 + half * 8 + (lane >> 2);
            float rs = rinv[row];
            __nv_bfloat16* dst = g_ag + (size_t)(mbase + row) * DV;
#pragma unroll
            for (int nt = 0; nt < 8; nt++) {
                int col = pn * 64 + nt * 8 + (lane & 3) * 2;
                *(__nv_bfloat162*)(dst + col) = __floats2bfloat162_rn(
                    O[mt][nt][half * 2 + 0] * rs, O[mt][nt][half * 2 + 1] * rs);
            }
        }
    }
}

// ---------------- prep: xconv (slice) + optional weight pack ----------------
__global__ void prep_kernel(const float* __restrict__ x,
                            const float* __restrict__ wt, const float* __restrict__ wp,
                            const float* __restrict__ wg, const float* __restrict__ bt,
                            const float* __restrict__ bp, const float* __restrict__ bg,
                            const float* __restrict__ wo,
                            int xblocks, int xoff) {
    int bx = blockIdx.x;
    if (bx < xblocks) {
        int i = (bx + xoff) * blockDim.x + threadIdx.x;  // 8 elems each
        float4 a = *(const float4*)(x + (size_t)i * 8);
        float4 b = *(const float4*)(x + (size_t)i * 8 + 4);
        __nv_bfloat162 h[4];
        h[0] = __floats2bfloat162_rn(a.x, a.y);
        h[1] = __floats2bfloat162_rn(a.z, a.w);
        h[2] = __floats2bfloat162_rn(b.x, b.y);
        h[3] = __floats2bfloat162_rn(b.z, b.w);
        *(uint4*)(g_xb + (size_t)i * 8) = *(uint4*)h;
        return;
    }
    int idx = (bx - xblocks) * blockDim.x + threadIdx.x;
    if (idx < NPROJ * CCH) {
        int n = idx / CCH, k = idx - n * CCH;
        float v;
        if (n < 64)       v = wt[k * 64 + n];
        else if (n < 128) v = wp[k * 64 + (n - 64)];
        else              v = wg[k * 256 + (n - 128)];
        g_wcatT[idx] = __float2bfloat16(v);
    }
    if (idx < CCH * DV) {
        int n = idx / DV, k = idx - n * DV;
        g_woT[idx] = __float2bfloat16(wo[k * CCH + n]);
    }
    if (idx < NPROJ) {
        float v;
        if (idx < 64)       v = bt[idx];
        else if (idx < 128) v = bp[idx - 64];
        else                v = bg[idx - 128];
        g_bcat[idx] = v;
    }
}

// ---------------- streams/events (host objects; created once pre-main) -----
static cudaStream_t g_s[3];
static cudaEvent_t g_evFork, g_evW, g_evJoin[3];
static struct StreamInit {
    StreamInit() {
        for (int i = 0; i < 3; i++)
            cudaStreamCreateWithFlags(&g_s[i], cudaStreamNonBlocking);
        cudaEventCreateWithFlags(&g_evFork, cudaEventDisableTiming);
        cudaEventCreateWithFlags(&g_evW, cudaEventDisableTiming);
        for (int i = 0; i < 3; i++)
            cudaEventCreateWithFlags(&g_evJoin[i], cudaEventDisableTiming);
    }
} g_stream_init;

// ---------------- launcher ----------------
#define XQ_BLOCKS (M_PIX * CCH / 8 / 256 / 4)   // 4096 xconv blocks per quarter
extern "C" void kernel_launch(void* const* d_in, const int* in_sizes, int n_in,
                              void* d_out, int out_size) {
    const float* x       = (const float*)d_in[0];
    const float* w_theta = (const float*)d_in[1];
    const float* b_theta = (const float*)d_in[2];
    const float* w_phi   = (const float*)d_in[3];
    const float* b_phi   = (const float*)d_in[4];
    const float* w_g     = (const float*)d_in[5];
    const float* b_g     = (const float*)d_in[6];
    const float* w_o     = (const float*)d_in[7];
    const float* b_o     = (const float*)d_in[8];
    const float* sigma   = (const float*)d_in[9];
    float* out = (float*)d_out;

    const int SMEM128 = 98304;
    cudaFuncSetAttribute((const void*)gemm128<0>, cudaFuncAttributeMaxDynamicSharedMemorySize, SMEM128);
    cudaFuncSetAttribute((const void*)gemm128<2>, cudaFuncAttributeMaxDynamicSharedMemorySize, SMEM128);
    cudaFuncSetAttribute((const void*)attn_fused, cudaFuncAttributeMaxDynamicSharedMemorySize, ATTN_SMEM);

    __nv_bfloat16 *xb, *ag, *wcatT, *woT;
    float* bcat;
    cudaGetSymbolAddress((void**)&xb, g_xb);
    cudaGetSymbolAddress((void**)&ag, g_ag);
    cudaGetSymbolAddress((void**)&wcatT, g_wcatT);
    cudaGetSymbolAddress((void**)&woT, g_woT);
    cudaGetSymbolAddress((void**)&bcat, g_bcat);

    // fork side streams off the capture (default) stream
    cudaEventRecord(g_evFork, 0);
    for (int i = 0; i < 3; i++) cudaStreamWaitEvent(g_s[i], g_evFork, 0);

    // ---- quarter 0 on default stream; carries weight packing ----
    prep_kernel<<<XQ_BLOCKS + (NPROJ * CCH + 255) / 256, 256>>>(
        x, w_theta, w_phi, w_g, b_theta, b_phi, b_g, w_o, XQ_BLOCKS, 0);
    cudaEventRecord(g_evW, 0);

    gemm128<0><<<dim3(NPROJ / 128, 128), 256, SMEM128>>>(
        xb, CCH, wcatT, CCH, CCH, 0, bcat, nullptr, nullptr, nullptr);
    attn_fused<<<256, 256, ATTN_SMEM>>>(0);
    gemm128<2><<<dim3(CCH / 128, 128), 256, SMEM128>>>(
        ag, DV, woT, DV, DV, 0, b_o, x, sigma, out);

    // ---- quarters 1..3 on side streams ----
    for (int q = 1; q < 4; q++) {
        cudaStream_t s = g_s[q - 1];
        prep_kernel<<<XQ_BLOCKS, 256, 0, s>>>(
            x, w_theta, w_phi, w_g, b_theta, b_phi, b_g, w_o,
            XQ_BLOCKS, XQ_BLOCKS * q);
        cudaStreamWaitEvent(s, g_evW, 0);   // needs packed weights
        gemm128<0><<<dim3(NPROJ / 128, 128), 256, SMEM128, s>>>(
            xb, CCH, wcatT, CCH, CCH, 128 * q, bcat, nullptr, nullptr, nullptr);
        attn_fused<<<256, 256, ATTN_SMEM, s>>>(256 * q);
        gemm128<2><<<dim3(CCH / 128, 128), 256, SMEM128, s>>>(
            ag, DV, woT, DV, DV, 128 * q, b_o, x, sigma, out);
        cudaEventRecord(g_evJoin[q - 1], s);
    }

    // join
    for (int i = 0; i < 3; i++) cudaStreamWaitEvent(0, g_evJoin[i], 0);
}

// round 15
// speedup vs baseline: 1.0582x; 1.0582x over previous
#include <cuda_runtime.h>
#include <cuda_bf16.h>
#include <cuda.h>
#include <cstdint>

#define BBATCH 16
#define CCH 512
#define M_PIX (BBATCH*64*64)     // 65536
#define NPROJ 384
#define DK 64
#define DV 256
#define NKV 1024
#define NQ  4096
#define LOG2E 1.4426950408889634f

// ---------------- scratch (device globals) ----------------
__device__ __align__(256) __nv_bfloat16 g_xb   [M_PIX * CCH];       // x in bf16
__device__ __align__(256) __nv_bfloat16 g_theta[M_PIX * DK];        // theta*log2e [q][64]
__device__ __align__(256) __nv_bfloat16 g_phi  [BBATCH * NKV * DK]; // pooled phi [kv][d]
__device__ __align__(256) __nv_bfloat16 g_gT   [BBATCH * DV * NKV]; // pooled g^T [d][kv]
__device__ __align__(256) __nv_bfloat16 g_ag   [M_PIX * DV];        // attn out bf16
__device__ __align__(256) __nv_bfloat16 g_wcatT[NPROJ * CCH];       // proj weights^T
__device__ __align__(256) __nv_bfloat16 g_woT  [CCH * DV];          // w_o^T
__device__ float g_bcat[NPROJ];

// ---------------- helpers ----------------
__device__ __forceinline__ uint32_t smem_u32(const void* p) {
    uint32_t a;
    asm("{ .reg .u64 t; cvta.to.shared.u64 t, %1; cvt.u32.u64 %0, t; }" : "=r"(a) : "l"(p));
    return a;
}
#define SWZ(o) ((o) ^ (((o) >> 3) & 0x70))

__device__ __forceinline__ void ldsm_x4(uint32_t* r, uint32_t a) {
    asm volatile("ldmatrix.sync.aligned.m8n8.x4.shared.b16 {%0,%1,%2,%3}, [%4];"
        : "=r"(r[0]), "=r"(r[1]), "=r"(r[2]), "=r"(r[3]) : "r"(a));
}
__device__ __forceinline__ void mma16816(float* d, const uint32_t* a, uint32_t b0, uint32_t b1) {
    asm volatile("mma.sync.aligned.m16n8k16.row.col.f32.bf16.bf16.f32 "
        "{%0,%1,%2,%3}, {%4,%5,%6,%7}, {%8,%9}, {%0,%1,%2,%3};"
        : "+f"(d[0]), "+f"(d[1]), "+f"(d[2]), "+f"(d[3])
        : "r"(a[0]), "r"(a[1]), "r"(a[2]), "r"(a[3]), "r"(b0), "r"(b1));
}
__device__ __forceinline__ float ex2(float x) {
    float r;
    asm("ex2.approx.ftz.f32 %0, %1;" : "=f"(r) : "f"(x));
    return r;
}

// ---- mbarrier / TMA ----
#define MBAR_INIT(addr, cnt) \
    asm volatile("mbarrier.init.shared.b64 [%0], %1;" :: "r"((uint32_t)(addr)), "r"((uint32_t)(cnt)) : "memory")
#define MBAR_EXPECT(addr, bytes) \
    asm volatile("mbarrier.arrive.expect_tx.shared.b64 _, [%0], %1;" :: "r"((uint32_t)(addr)), "r"((uint32_t)(bytes)) : "memory")
#define MBAR_WAIT(addr, par) do {                                                    \
    uint32_t _m = (uint32_t)(addr); uint32_t _p = (uint32_t)(par); uint32_t _d;      \
    asm volatile("{\n\t.reg .pred p;\n\t"                                            \
        "mbarrier.try_wait.parity.acquire.cta.shared::cta.b64 p, [%1], %2;\n\t"      \
        "selp.b32 %0, 1, 0, p;\n\t}" : "=r"(_d) : "r"(_m), "r"(_p) : "memory");      \
    if (!_d) {                                                                       \
        asm volatile("{\n\t.reg .pred P1;\n\tWL_%=:\n\t"                             \
            "mbarrier.try_wait.parity.acquire.cta.shared::cta.b64 P1, [%0], %1, 0x989680;\n\t" \
            "@P1 bra.uni WD_%=;\n\tbra.uni WL_%=;\n\tWD_%=:\n\t}"                    \
            :: "r"(_m), "r"(_p) : "memory");                                         \
    } } while (0)
#define FENCE_ASYNC_SHARED() asm volatile("fence.proxy.async.shared::cta;" ::: "memory")
#define TMA2D(dst, mapp, cx, cy, mbar) \
    asm volatile("cp.async.bulk.tensor.2d.shared::cta.global.tile.mbarrier::complete_tx::bytes " \
                 "[%0], [%1, {%2, %3}], [%4];" \
                 :: "r"((uint32_t)(dst)), "l"(mapp), "r"((int)(cx)), "r"((int)(cy)), \
                    "r"((uint32_t)(mbar)) : "memory")

// ------------- 128x128-tile bf16 HMMA GEMM, fp32 accum, 3-buffer TMA --------
// MODE 0: proj — theta(*log2e) direct + pooled phi + pooled/transposed gT (+bias)
// MODE 2: fp32 out = X + sig*(D+bias), x tile TMA-staged in last chunk
template <int MODE>
__global__ void __launch_bounds__(256, 2)
gemm128(const __grid_constant__ CUtensorMap tmA,
        const __grid_constant__ CUtensorMap tmB,
        const __grid_constant__ CUtensorMap tmX,
        int K, int moff,
        const float* __restrict__ bias,
        const float* __restrict__ sig,
        float* __restrict__ outf) {
    extern __shared__ __align__(1024) char sm[];
    uint32_t base = smem_u32(sm);
    const uint32_t a_su[3] = {base, base + 16384, base + 32768};
    const uint32_t b_su[3] = {base + 49152, base + 65536, base + 81920};
    // x staging (MODE 2, last chunk): 64KB spanning bufs 1+2 of A and B regions
    const uint32_t x_su[2] = {base + 16384, base + 65536};
    const uint32_t mb = base + 98304;   // mbarriers: +0,+8,+16 (chunks), +24 (x)

    int tid = threadIdx.x, wid = tid >> 5, lane = tid & 31;
    int m0 = (blockIdx.y + moff) * 128, n0 = blockIdx.x * 128;
    int wm = wid & 3, wn = wid >> 2;
    int lr = lane & 15, lc = lane >> 4;

    float acc[2][8][4];
#pragma unroll
    for (int i = 0; i < 2; i++)
#pragma unroll
        for (int j = 0; j < 8; j++)
#pragma unroll
            for (int e = 0; e < 4; e++) acc[i][j][e] = 0.f;

    const int nc = K >> 6;
    if (tid == 0) {
        MBAR_INIT(mb + 0, 1); MBAR_INIT(mb + 8, 1); MBAR_INIT(mb + 16, 1);
        if (MODE == 2) MBAR_INIT(mb + 24, 1);
        FENCE_ASYNC_SHARED();
    }
    __syncthreads();
    if (tid == 0) {
        MBAR_EXPECT(mb + 0, 32768);
        TMA2D(a_su[0], &tmA, 0, m0, mb + 0);
        TMA2D(b_su[0], &tmB, 0, n0, mb + 0);
        MBAR_EXPECT(mb + 8, 32768);
        TMA2D(a_su[1], &tmA, 64, m0, mb + 8);
        TMA2D(b_su[1], &tmB, 64, n0, mb + 8);
    }

#pragma unroll 3
    for (int c = 0; c < nc; c++) {
        MBAR_WAIT(mb + 8 * (c % 3), (c / 3) & 1);
        __syncthreads();   // all warps done with chunk c-1 buffers

        if (tid == 0) {
            if (c + 2 < nc) {
                int nb = (c + 2) % 3;
                MBAR_EXPECT(mb + 8 * nb, 32768);
                TMA2D(a_su[nb], &tmA, (c + 2) * 64, m0, mb + 8 * nb);
                TMA2D(b_su[nb], &tmB, (c + 2) * 64, n0, mb + 8 * nb);
            }
            if (MODE == 2 && c == nc - 1) {
                // bufs 1+2 consumed; stage fp32 x tile (128x128 = 64KB)
                MBAR_EXPECT(mb + 24, 65536);
                TMA2D(x_su[0], &tmX, n0, m0, mb + 24);
                TMA2D(x_su[1], &tmX, n0, m0 + 64, mb + 24);
            }
        }

        int buf = c % 3;
        uint32_t abase = a_su[buf], bbase = b_su[buf];
#pragma unroll
        for (int k16 = 0; k16 < 4; k16++) {
            uint32_t af[2][4];
#pragma unroll
            for (int mt = 0; mt < 2; mt++)
                ldsm_x4(af[mt], abase + SWZ((wm * 32 + mt * 16 + lr) * 128 + k16 * 32 + lc * 16));
            uint32_t bf4[4][4];
#pragma unroll
            for (int nt2 = 0; nt2 < 4; nt2++)
                ldsm_x4(bf4[nt2], bbase + SWZ((wn * 64 + nt2 * 16 + lr) * 128 + k16 * 32 + lc * 16));
#pragma unroll
            for (int mt = 0; mt < 2; mt++)
#pragma unroll
                for (int nt = 0; nt < 8; nt++)
                    mma16816(acc[mt][nt], af[mt], bf4[nt >> 1][nt & 1], bf4[nt >> 1][2 + (nt & 1)]);
        }
    }

    if (MODE == 2) {
        MBAR_WAIT(mb + 24, 0);   // x staging landed
        __syncthreads();
        float s = sig[0];
        int r0l = wm * 32 + (lane >> 2);
        int c0 = wn * 64 + (lane & 3) * 2;
#pragma unroll
        for (int mt = 0; mt < 2; mt++) {
#pragma unroll
            for (int half = 0; half < 2; half++) {
                int rowl = r0l + mt * 16 + half * 8;
                uint32_t xrow = x_su[rowl >> 6] + (rowl & 63) * 512;
                int grow = m0 + rowl;
#pragma unroll
                for (int nt = 0; nt < 8; nt++) {
                    int col = c0 + nt * 8;
                    float2 xv = *(const float2*)(sm + (xrow - base) + col * 4);
                    float2 o;
                    o.x = xv.x + s * (acc[mt][nt][half * 2 + 0] + bias[n0 + col]);
                    o.y = xv.y + s * (acc[mt][nt][half * 2 + 1] + bias[n0 + col + 1]);
                    *(float2*)(outf + (size_t)grow * CCH + n0 + col) = o;
                }
            }
        }
    }

    if (MODE == 0) {
        // proj epilogue with fused pooling
        int b = m0 >> 12;
        int kv0 = ((m0 >> 7) & 31) * 32;   // 32 pool windows per tile
        __nv_bfloat16* st = (__nv_bfloat16*)sm;
        __syncthreads();

        if (blockIdx.x == 0) {
            if (wn == 0) {
                // theta, pre-scaled by log2e for ex2-based softmax
#pragma unroll
                for (int mt = 0; mt < 2; mt++)
#pragma unroll
                    for (int half = 0; half < 2; half++) {
                        int row = m0 + wm * 32 + (lane >> 2) + mt * 16 + half * 8;
#pragma unroll
                        for (int nt = 0; nt < 8; nt++) {
                            int col = nt * 8 + (lane & 3) * 2;
                            *(__nv_bfloat162*)(g_theta + (size_t)row * DK + col) =
                                __floats2bfloat162_rn(
                                    (acc[mt][nt][half * 2] + bias[col]) * LOG2E,
                                    (acc[mt][nt][half * 2 + 1] + bias[col + 1]) * LOG2E);
                        }
                    }
            } else {
#pragma unroll
                for (int mt = 0; mt < 2; mt++)
#pragma unroll
                    for (int half = 0; half < 2; half++) {
                        int lrow = wm * 32 + (lane >> 2) + mt * 16 + half * 8;
#pragma unroll
                        for (int nt = 0; nt < 8; nt++) {
                            int lcol = nt * 8 + (lane & 3) * 2;   // 0..63
                            *(__nv_bfloat162*)(st + lrow * 72 + lcol) =
                                __floats2bfloat162_rn(acc[mt][nt][half * 2] + bias[64 + lcol],
                                                      acc[mt][nt][half * 2 + 1] + bias[65 + lcol]);
                        }
                    }
            }
            __syncthreads();
            int w = tid >> 3, d8 = (tid & 7) * 8;
            __align__(16) __nv_bfloat16 o[8];
#pragma unroll
            for (int j = 0; j < 8; j++) {
                int d = d8 + j;
                o[j] = __hmax(__hmax(st[(2 * w) * 72 + d], st[(2 * w + 1) * 72 + d]),
                              __hmax(st[(64 + 2 * w) * 72 + d], st[(65 + 2 * w) * 72 + d]));
            }
            *(uint4*)(g_phi + ((size_t)(b * NKV + kv0 + w)) * DK + d8) = *(uint4*)o;
        } else {
#pragma unroll
            for (int mt = 0; mt < 2; mt++)
#pragma unroll
                for (int half = 0; half < 2; half++) {
                    int lrow = wm * 32 + (lane >> 2) + mt * 16 + half * 8;
#pragma unroll
                    for (int nt = 0; nt < 8; nt++) {
                        int lcol = wn * 64 + nt * 8 + (lane & 3) * 2;   // 0..127
                        *(__nv_bfloat162*)(st + lrow * 130 + lcol) =
                            __floats2bfloat162_rn(acc[mt][nt][half * 2] + bias[n0 + lcol],
                                                  acc[mt][nt][half * 2 + 1] + bias[n0 + lcol + 1]);
                    }
                }
            __syncthreads();
            int dl = tid & 127, kvh = tid >> 7;
            int dg = (blockIdx.x - 1) * 128 + dl;
            __align__(16) __nv_bfloat16 o[16];
#pragma unroll
            for (int i = 0; i < 16; i++) {
                int w = kvh * 16 + i;
                o[i] = __hmax(__hmax(st[(2 * w) * 130 + dl], st[(2 * w + 1) * 130 + dl]),
                              __hmax(st[(64 + 2 * w) * 130 + dl], st[(65 + 2 * w) * 130 + dl]));
            }
            __nv_bfloat16* dst = g_gT + ((size_t)(b * DV + dg)) * NKV + kv0 + kvh * 16;
            *(uint4*)dst = ((uint4*)o)[0];
            *(uint4*)(dst + 8) = ((uint4*)o)[1];
        }
    }
}

// ------------- fused attention: ag = softmax(theta phi^T) g, TMA loads ------
#define ATTN_SMEM (99104)
__global__ void __launch_bounds__(256, 2)
attn_fused(const __grid_constant__ CUtensorMap tmT,
           const __grid_constant__ CUtensorMap tmP,
           const __grid_constant__ CUtensorMap tmG,
           int toff) {
    extern __shared__ __align__(1024) char sm[];
    uint32_t base = smem_u32(sm);
    const uint32_t th_s = base;
    const uint32_t ph_s[2] = {base + 8192, base + 16384};
    const uint32_t gt_s[2] = {base + 24576, base + 57344};
    const uint32_t p_s = base + 90112;
    float* wsum = (float*)(sm + 98304);   // [2][64]
    float* rinv = (float*)(sm + 98816);   // [64]
    const uint32_t mb = base + 99072;     // mbarriers: +0, +8

    int tid = threadIdx.x, wid = tid >> 5, lane = tid & 31;
    int lr = lane & 15, lc = lane >> 4;
    int tile = blockIdx.x + toff;
    int mbase = tile * 64;
    int b = tile >> 6;
    int wm = wid & 3, wn = wid >> 2;       // S phase
    int pm = wid & 1, pn = wid >> 1;       // PV phase

    float O[2][8][4];
#pragma unroll
    for (int i = 0; i < 2; i++)
#pragma unroll
        for (int j = 0; j < 8; j++)
#pragma unroll
            for (int e = 0; e < 4; e++) O[i][j][e] = 0.f;
    float sum0 = 0.f, sum1 = 0.f;

    if (tid == 0) {
        MBAR_INIT(mb + 0, 1); MBAR_INIT(mb + 8, 1);
        FENCE_ASYNC_SHARED();
    }
    __syncthreads();
    if (tid == 0) {
        MBAR_EXPECT(mb + 0, 49152);            // theta + phi0 + gT0
        TMA2D(th_s, &tmT, 0, mbase, mb + 0);
        TMA2D(ph_s[0], &tmP, 0, b * NKV, mb + 0);
        TMA2D(gt_s[0], &tmG, 0, b * DV, mb + 0);
    }

    for (int c = 0; c < 16; c++) {
        MBAR_WAIT(mb + 8 * (c & 1), (c >> 1) & 1);
        __syncthreads();   // chunk-c tiles visible; all warps done with c-1

        if (tid == 0 && c + 1 < 16) {          // prefetch c+1
            int nb = (c + 1) & 1;
            MBAR_EXPECT(mb + 8 * nb, 40960);   // phi + gT
            TMA2D(ph_s[nb], &tmP, 0, b * NKV + (c + 1) * 64, mb + 8 * nb);
            TMA2D(gt_s[nb], &tmG, (c + 1) * 64, b * DV, mb + 8 * nb);
        }

        // ---- S phase ----
        float sacc[4][4];
#pragma unroll
        for (int j = 0; j < 4; j++)
#pragma unroll
            for (int e = 0; e < 4; e++) sacc[j][e] = 0.f;
        uint32_t pb = ph_s[c & 1];
#pragma unroll
        for (int k16 = 0; k16 < 4; k16++) {
            uint32_t af[4];
            ldsm_x4(af, th_s + SWZ((wm * 16 + lr) * 128 + k16 * 32 + lc * 16));
            uint32_t bf2[2][4];
#pragma unroll
            for (int nt2 = 0; nt2 < 2; nt2++)
                ldsm_x4(bf2[nt2], pb + SWZ((wn * 32 + nt2 * 16 + lr) * 128 + k16 * 32 + lc * 16));
#pragma unroll
            for (int nt = 0; nt < 4; nt++)
                mma16816(sacc[nt], af, bf2[nt >> 1][nt & 1], bf2[nt >> 1][2 + (nt & 1)]);
        }

        int srow = wm * 16 + (lane >> 2);
#pragma unroll
        for (int nt = 0; nt < 4; nt++) {
            int scol = wn * 32 + nt * 8 + (lane & 3) * 2;
            float e0 = ex2(sacc[nt][0]);
            float e1 = ex2(sacc[nt][1]);
            float e2 = ex2(sacc[nt][2]);
            float e3 = ex2(sacc[nt][3]);
            sum0 += e0 + e1;
            sum1 += e2 + e3;
            *(__nv_bfloat162*)(sm + (p_s - base) + SWZ(srow * 128 + scol * 2)) =
                __floats2bfloat162_rn(e0, e1);
            *(__nv_bfloat162*)(sm + (p_s - base) + SWZ((srow + 8) * 128 + scol * 2)) =
                __floats2bfloat162_rn(e2, e3);
        }
        __syncthreads();   // P(c) visible to all warps

        // ---- PV phase ----
        uint32_t gb = gt_s[c & 1];
#pragma unroll
        for (int k16 = 0; k16 < 4; k16++) {
            uint32_t paf[2][4];
#pragma unroll
            for (int mt = 0; mt < 2; mt++)
                ldsm_x4(paf[mt], p_s + SWZ((pm * 32 + mt * 16 + lr) * 128 + k16 * 32 + lc * 16));
            uint32_t gbf[4][4];
#pragma unroll
            for (int nt2 = 0; nt2 < 4; nt2++)
                ldsm_x4(gbf[nt2], gb + SWZ((pn * 64 + nt2 * 16 + lr) * 128 + k16 * 32 + lc * 16));
#pragma unroll
            for (int mt = 0; mt < 2; mt++)
#pragma unroll
                for (int nt = 0; nt < 8; nt++)
                    mma16816(O[mt][nt], paf[mt], gbf[nt >> 1][nt & 1], gbf[nt >> 1][2 + (nt & 1)]);
        }
    }

    // deterministic row-sum reduction
    sum0 += __shfl_xor_sync(0xffffffffu, sum0, 1);
    sum0 += __shfl_xor_sync(0xffffffffu, sum0, 2);
    sum1 += __shfl_xor_sync(0xffffffffu, sum1, 1);
    sum1 += __shfl_xor_sync(0xffffffffu, sum1, 2);
    if ((lane & 3) == 0) {
        wsum[wn * 64 + wm * 16 + (lane >> 2)] = sum0;
        wsum[wn * 64 + wm * 16 + 8 + (lane >> 2)] = sum1;
    }
    __syncthreads();
    if (tid < 64) rinv[tid] = 1.f / (wsum[tid] + wsum[64 + tid]);
    __syncthreads();

#pragma unroll
    for (int mt = 0; mt < 2; mt++) {
#pragma unroll
        for (int half = 0; half < 2; half++) {
            int row = pm * 32 + mt * 16 + half * 8 + (lane >> 2);
            float rs = rinv[row];
            __nv_bfloat16* dst = g_ag + (size_t)(mbase + row) * DV;
#pragma unroll
            for (int nt = 0; nt < 8; nt++) {
                int col = pn * 64 + nt * 8 + (lane & 3) * 2;
                *(__nv_bfloat162*)(dst + col) = __floats2bfloat162_rn(
                    O[mt][nt][half * 2 + 0] * rs, O[mt][nt][half * 2 + 1] * rs);
            }
        }
    }
}

// ---------------- prep: xconv (slice) + optional weight pack ----------------
__global__ void prep_kernel(const float* __restrict__ x,
                            const float* __restrict__ wt, const float* __restrict__ wp,
                            const float* __restrict__ wg, const float* __restrict__ bt,
                            const float* __restrict__ bp, const float* __restrict__ bg,
                            const float* __restrict__ wo,
                            int xblocks, int xoff) {
    int bx = blockIdx.x;
    if (bx < xblocks) {
        int i = (bx + xoff) * blockDim.x + threadIdx.x;  // 8 elems each
        float4 a = *(const float4*)(x + (size_t)i * 8);
        float4 b = *(const float4*)(x + (size_t)i * 8 + 4);
        __nv_bfloat162 h[4];
        h[0] = __floats2bfloat162_rn(a.x, a.y);
        h[1] = __floats2bfloat162_rn(a.z, a.w);
        h[2] = __floats2bfloat162_rn(b.x, b.y);
        h[3] = __floats2bfloat162_rn(b.z, b.w);
        *(uint4*)(g_xb + (size_t)i * 8) = *(uint4*)h;
        return;
    }
    int idx = (bx - xblocks) * blockDim.x + threadIdx.x;
    if (idx < NPROJ * CCH) {
        int n = idx / CCH, k = idx - n * CCH;
        float v;
        if (n < 64)       v = wt[k * 64 + n];
        else if (n < 128) v = wp[k * 64 + (n - 64)];
        else              v = wg[k * 256 + (n - 128)];
        g_wcatT[idx] = __float2bfloat16(v);
    }
    if (idx < CCH * DV) {
        int n = idx / DV, k = idx - n * DV;
        g_woT[idx] = __float2bfloat16(wo[k * CCH + n]);
    }
    if (idx < NPROJ) {
        float v;
        if (idx < 64)       v = bt[idx];
        else if (idx < 128) v = bp[idx - 64];
        else                v = bg[idx - 128];
        g_bcat[idx] = v;
    }
}

// ---------------- host: streams + tensormap encode ----------------
static cudaStream_t g_s2;
static cudaEvent_t g_evFork, g_evW, g_evJoin;
static struct StreamInit {
    StreamInit() {
        cudaStreamCreateWithFlags(&g_s2, cudaStreamNonBlocking);
        cudaEventCreateWithFlags(&g_evFork, cudaEventDisableTiming);
        cudaEventCreateWithFlags(&g_evW, cudaEventDisableTiming);
        cudaEventCreateWithFlags(&g_evJoin, cudaEventDisableTiming);
    }
} g_stream_init;

typedef CUresult (*EncFn)(CUtensorMap*, CUtensorMapDataType, cuuint32_t, void*,
                          const cuuint64_t*, const cuuint64_t*, const cuuint32_t*,
                          const cuuint32_t*, CUtensorMapInterleave, CUtensorMapSwizzle,
                          CUtensorMapL2promotion, CUtensorMapFloatOOBfill);
static EncFn get_enc() {
    static EncFn fn = nullptr;
    if (!fn) {
        cudaDriverEntryPointQueryResult qr;
        cudaGetDriverEntryPoint("cuTensorMapEncodeTiled", (void**)&fn,
                                cudaEnableDefault, &qr);
    }
    return fn;
}
static void make2d(CUtensorMap* tm, void* ptr, CUtensorMapDataType dt,
                   uint64_t d0, uint64_t d1, uint64_t rowbytes,
                   uint32_t b0, uint32_t b1, CUtensorMapSwizzle sw) {
    cuuint64_t dims[2] = {d0, d1};
    cuuint64_t strides[1] = {rowbytes};
    cuuint32_t box[2] = {b0, b1};
    cuuint32_t es[2] = {1, 1};
    get_enc()(tm, dt, 2, ptr, dims, strides, box, es,
              CU_TENSOR_MAP_INTERLEAVE_NONE, sw,
              CU_TENSOR_MAP_L2_PROMOTION_L2_128B, CU_TENSOR_MAP_FLOAT_OOB_FILL_NONE);
}

// ---------------- launcher (halves) ----------------
#define XHALF_BLOCKS (M_PIX * CCH / 8 / 256 / 2)   // 8192
extern "C" void kernel_launch(void* const* d_in, const int* in_sizes, int n_in,
                              void* d_out, int out_size) {
    const float* x       = (const float*)d_in[0];
    const float* w_theta = (const float*)d_in[1];
    const float* b_theta = (const float*)d_in[2];
    const float* w_phi   = (const float*)d_in[3];
    const float* b_phi   = (const float*)d_in[4];
    const float* w_g     = (const float*)d_in[5];
    const float* b_g     = (const float*)d_in[6];
    const float* w_o     = (const float*)d_in[7];
    const float* b_o     = (const float*)d_in[8];
    const float* sigma   = (const float*)d_in[9];
    float* out = (float*)d_out;

    const int SMEM128 = 98304 + 64;
    cudaFuncSetAttribute((const void*)gemm128<0>, cudaFuncAttributeMaxDynamicSharedMemorySize, SMEM128);
    cudaFuncSetAttribute((const void*)gemm128<2>, cudaFuncAttributeMaxDynamicSharedMemorySize, SMEM128);
    cudaFuncSetAttribute((const void*)attn_fused, cudaFuncAttributeMaxDynamicSharedMemorySize, ATTN_SMEM);

    __nv_bfloat16 *xb, *theta, *phi, *gT, *ag, *wcatT, *woT;
    float* bcat;
    cudaGetSymbolAddress((void**)&xb, g_xb);
    cudaGetSymbolAddress((void**)&theta, g_theta);
    cudaGetSymbolAddress((void**)&phi, g_phi);
    cudaGetSymbolAddress((void**)&gT, g_gT);
    cudaGetSymbolAddress((void**)&ag, g_ag);
    cudaGetSymbolAddress((void**)&wcatT, g_wcatT);
    cudaGetSymbolAddress((void**)&woT, g_woT);
    cudaGetSymbolAddress((void**)&bcat, g_bcat);

    CUtensorMap tmXb, tmWc, tmAg, tmWo, tmX, tmTh, tmPh, tmGt;
    make2d(&tmXb, xb, CU_TENSOR_MAP_DATA_TYPE_BFLOAT16, CCH, M_PIX, CCH * 2, 64, 128,
           CU_TENSOR_MAP_SWIZZLE_128B);
    make2d(&tmWc, wcatT, CU_TENSOR_MAP_DATA_TYPE_BFLOAT16, CCH, NPROJ, CCH * 2, 64, 128,
           CU_TENSOR_MAP_SWIZZLE_128B);
    make2d(&tmAg, ag, CU_TENSOR_MAP_DATA_TYPE_BFLOAT16, DV, M_PIX, DV * 2, 64, 128,
           CU_TENSOR_MAP_SWIZZLE_128B);
    make2d(&tmWo, woT, CU_TENSOR_MAP_DATA_TYPE_BFLOAT16, DV, CCH, DV * 2, 64, 128,
           CU_TENSOR_MAP_SWIZZLE_128B);
    make2d(&tmX, (void*)x, CU_TENSOR_MAP_DATA_TYPE_FLOAT32, CCH, M_PIX, CCH * 4, 128, 64,
           CU_TENSOR_MAP_SWIZZLE_NONE);
    make2d(&tmTh, theta, CU_TENSOR_MAP_DATA_TYPE_BFLOAT16, DK, M_PIX, DK * 2, 64, 64,
           CU_TENSOR_MAP_SWIZZLE_128B);
    make2d(&tmPh, phi, CU_TENSOR_MAP_DATA_TYPE_BFLOAT16, DK, BBATCH * NKV, DK * 2, 64, 64,
           CU_TENSOR_MAP_SWIZZLE_128B);
    make2d(&tmGt, gT, CU_TENSOR_MAP_DATA_TYPE_BFLOAT16, NKV, BBATCH * DV, NKV * 2, 64, 256,
           CU_TENSOR_MAP_SWIZZLE_128B);

    // fork second stream off the capture (default) stream
    cudaEventRecord(g_evFork, 0);
    cudaStreamWaitEvent(g_s2, g_evFork, 0);

    // ---- half A (batches 0-7) on default stream; carries weight packing ----
    prep_kernel<<<XHALF_BLOCKS + (NPROJ * CCH + 255) / 256, 256>>>(
        x, w_theta, w_phi, w_g, b_theta, b_phi, b_g, w_o, XHALF_BLOCKS, 0);
    cudaEventRecord(g_evW, 0);

    gemm128<0><<<dim3(NPROJ / 128, 256), 256, SMEM128>>>(
        tmXb, tmWc, tmX, CCH, 0, bcat, nullptr, nullptr);
    attn_fused<<<512, 256, ATTN_SMEM>>>(tmTh, tmPh, tmGt, 0);
    gemm128<2><<<dim3(CCH / 128, 256), 256, SMEM128>>>(
        tmAg, tmWo, tmX, DV, 0, b_o, sigma, out);

    // ---- half B (batches 8-15) on second stream ----
    prep_kernel<<<XHALF_BLOCKS, 256, 0, g_s2>>>(
        x, w_theta, w_phi, w_g, b_theta, b_phi, b_g, w_o, XHALF_BLOCKS, XHALF_BLOCKS);
    cudaStreamWaitEvent(g_s2, g_evW, 0);   // needs packed weights
    gemm128<0><<<dim3(NPROJ / 128, 256), 256, SMEM128, g_s2>>>(
        tmXb, tmWc, tmX, CCH, 256, bcat, nullptr, nullptr);
    attn_fused<<<512, 256, ATTN_SMEM, g_s2>>>(tmTh, tmPh, tmGt, 512);
    gemm128<2><<<dim3(CCH / 128, 256), 256, SMEM128, g_s2>>>(
        tmAg, tmWo, tmX, DV, 256, b_o, sigma, out);

    // join
    cudaEventRecord(g_evJoin, g_s2);
    cudaStreamWaitEvent(0, g_evJoin, 0);
}